// round 5
// baseline (speedup 1.0000x reference)
#include <cuda_runtime.h>
#include <math.h>

static constexpr float EPS_CLIP = 1e-7f;
static constexpr float SCALE    = 64.0f;
// cos(0.5), sin(0.5)
static constexpr float COS_M = 0.8775825618903728f;
static constexpr float SIN_M = 0.479425538604203f;

// ---------------------------------------------------------------------------
// Fused single kernel.
//   - Each warp caches the full W (2x512 f32) in registers: lane holds
//     w0[k] = W4[lane + 32k], w1[k] = W4[128 + lane + 32k], k=0..3.
//   - Warp-reduces ||W0||^2, ||W1||^2 once; folds inverse norms into the
//     final cosine (no need to scale the W registers).
//   - Grid-stride over rows, 2 rows per iteration for 8 independent
//     512B loads in flight per warp.
// ---------------------------------------------------------------------------
__global__ void __launch_bounds__(256)
arcface_fused_kernel(const float* __restrict__ feat,
                     const float* __restrict__ W,
                     const int*   __restrict__ label,
                     float*       __restrict__ out,
                     int B, int nwarps)
{
    const int gwarp = (blockIdx.x * blockDim.x + threadIdx.x) >> 5;
    const int lane  = threadIdx.x & 31;

    // ---- Per-warp W register cache + norm computation (amortized) ----
    const float4* __restrict__ W4 = reinterpret_cast<const float4*>(W);
    float4 w0[4], w1[4];
    float ssw0 = 0.0f, ssw1 = 0.0f;
    #pragma unroll
    for (int k = 0; k < 4; k++) {
        const int idx = lane + 32 * k;
        w0[k] = W4[idx];
        w1[k] = W4[128 + idx];
        ssw0 = fmaf(w0[k].x, w0[k].x, ssw0); ssw0 = fmaf(w0[k].y, w0[k].y, ssw0);
        ssw0 = fmaf(w0[k].z, w0[k].z, ssw0); ssw0 = fmaf(w0[k].w, w0[k].w, ssw0);
        ssw1 = fmaf(w1[k].x, w1[k].x, ssw1); ssw1 = fmaf(w1[k].y, w1[k].y, ssw1);
        ssw1 = fmaf(w1[k].z, w1[k].z, ssw1); ssw1 = fmaf(w1[k].w, w1[k].w, ssw1);
    }
    #pragma unroll
    for (int o = 16; o > 0; o >>= 1) {
        ssw0 += __shfl_xor_sync(0xffffffff, ssw0, o);
        ssw1 += __shfl_xor_sync(0xffffffff, ssw1, o);
    }
    const float invw0 = 1.0f / fmaxf(sqrtf(ssw0), 1e-12f);
    const float invw1 = 1.0f / fmaxf(sqrtf(ssw1), 1e-12f);

    // ---- Row loop: 2 rows per iteration ----
    for (int row = gwarp; row < B; row += 2 * nwarps) {
        const int row2 = row + nwarps;
        const bool has2 = (row2 < B);

        const float4* __restrict__ fA =
            reinterpret_cast<const float4*>(feat + (size_t)row * 512);
        const float4* __restrict__ fB =
            reinterpret_cast<const float4*>(feat + (size_t)(has2 ? row2 : row) * 512);

        float ssA = 0.0f, d0A = 0.0f, d1A = 0.0f;
        float ssB = 0.0f, d0B = 0.0f, d1B = 0.0f;

        // Front-batch all 8 loads for max MLP.
        float4 a[4], b[4];
        #pragma unroll
        for (int k = 0; k < 4; k++) {
            const int idx = lane + 32 * k;
            a[k] = fA[idx];
            b[k] = fB[idx];
        }

        #pragma unroll
        for (int k = 0; k < 4; k++) {
            ssA = fmaf(a[k].x, a[k].x, ssA); ssA = fmaf(a[k].y, a[k].y, ssA);
            ssA = fmaf(a[k].z, a[k].z, ssA); ssA = fmaf(a[k].w, a[k].w, ssA);
            d0A = fmaf(a[k].x, w0[k].x, d0A); d0A = fmaf(a[k].y, w0[k].y, d0A);
            d0A = fmaf(a[k].z, w0[k].z, d0A); d0A = fmaf(a[k].w, w0[k].w, d0A);
            d1A = fmaf(a[k].x, w1[k].x, d1A); d1A = fmaf(a[k].y, w1[k].y, d1A);
            d1A = fmaf(a[k].z, w1[k].z, d1A); d1A = fmaf(a[k].w, w1[k].w, d1A);

            ssB = fmaf(b[k].x, b[k].x, ssB); ssB = fmaf(b[k].y, b[k].y, ssB);
            ssB = fmaf(b[k].z, b[k].z, ssB); ssB = fmaf(b[k].w, b[k].w, ssB);
            d0B = fmaf(b[k].x, w0[k].x, d0B); d0B = fmaf(b[k].y, w0[k].y, d0B);
            d0B = fmaf(b[k].z, w0[k].z, d0B); d0B = fmaf(b[k].w, w0[k].w, d0B);
            d1B = fmaf(b[k].x, w1[k].x, d1B); d1B = fmaf(b[k].y, w1[k].y, d1B);
            d1B = fmaf(b[k].z, w1[k].z, d1B); d1B = fmaf(b[k].w, w1[k].w, d1B);
        }

        #pragma unroll
        for (int o = 16; o > 0; o >>= 1) {
            ssA += __shfl_xor_sync(0xffffffff, ssA, o);
            d0A += __shfl_xor_sync(0xffffffff, d0A, o);
            d1A += __shfl_xor_sync(0xffffffff, d1A, o);
            ssB += __shfl_xor_sync(0xffffffff, ssB, o);
            d0B += __shfl_xor_sync(0xffffffff, d0B, o);
            d1B += __shfl_xor_sync(0xffffffff, d1B, o);
        }

        if (lane == 0) {
            {
                const float invf = 1.0f / fmaxf(sqrtf(ssA), 1e-12f);
                float c0 = fminf(fmaxf(d0A * invf * invw0, -1.0f + EPS_CLIP), 1.0f - EPS_CLIP);
                float c1 = fminf(fmaxf(d1A * invf * invw1, -1.0f + EPS_CLIP), 1.0f - EPS_CLIP);
                float s0 = sqrtf(fmaxf(1.0f - c0 * c0, 0.0f));
                float s1 = sqrtf(fmaxf(1.0f - c1 * c1, 0.0f));
                float m0 = c0 * COS_M - s0 * SIN_M;
                float m1 = c1 * COS_M - s1 * SIN_M;
                const int lab = label[row];
                float o0 = (lab == 0) ? m0 : c0;
                float o1 = (lab == 1) ? m1 : c1;
                reinterpret_cast<float2*>(out)[row] =
                    make_float2(o0 * SCALE, o1 * SCALE);
            }
            if (has2) {
                const float invf = 1.0f / fmaxf(sqrtf(ssB), 1e-12f);
                float c0 = fminf(fmaxf(d0B * invf * invw0, -1.0f + EPS_CLIP), 1.0f - EPS_CLIP);
                float c1 = fminf(fmaxf(d1B * invf * invw1, -1.0f + EPS_CLIP), 1.0f - EPS_CLIP);
                float s0 = sqrtf(fmaxf(1.0f - c0 * c0, 0.0f));
                float s1 = sqrtf(fmaxf(1.0f - c1 * c1, 0.0f));
                float m0 = c0 * COS_M - s0 * SIN_M;
                float m1 = c1 * COS_M - s1 * SIN_M;
                const int lab = label[row2];
                float o0 = (lab == 0) ? m0 : c0;
                float o1 = (lab == 1) ? m1 : c1;
                reinterpret_cast<float2*>(out)[row2] =
                    make_float2(o0 * SCALE, o1 * SCALE);
            }
        }
    }
}

// ---------------------------------------------------------------------------
// kernel_launch: identify inputs by element count (robust to ordering):
//   feat  : B*D f32 (largest), W : C*D f32 (smallest), label : B int32
// ---------------------------------------------------------------------------
extern "C" void kernel_launch(void* const* d_in, const int* in_sizes, int n_in,
                              void* d_out, int out_size)
{
    int i_feat = 0, i_w = 0, i_lab = 0;
    for (int i = 1; i < n_in; i++) {
        if (in_sizes[i] > in_sizes[i_feat]) i_feat = i;
        if (in_sizes[i] < in_sizes[i_w])    i_w    = i;
    }
    for (int i = 0; i < n_in; i++)
        if (i != i_feat && i != i_w) i_lab = i;

    const float* feat  = (const float*)d_in[i_feat];
    const float* W     = (const float*)d_in[i_w];
    const int*   label = (const int*)d_in[i_lab];
    float*       out   = (float*)d_out;
    const int    B     = in_sizes[i_lab];

    const int blocks = 1024;                 // 8192 warps -> 16 rows/warp
    const int nwarps = blocks * (256 / 32);
    arcface_fused_kernel<<<blocks, 256>>>(feat, W, label, out, B, nwarps);
}

// round 6
// speedup vs baseline: 1.1188x; 1.1188x over previous
#include <cuda_runtime.h>
#include <math.h>

static constexpr float EPS_CLIP = 1e-7f;
static constexpr float SCALE    = 64.0f;
// cos(0.5), sin(0.5)
static constexpr float COS_M = 0.8775825618903728f;
static constexpr float SIN_M = 0.479425538604203f;

// ---------------------------------------------------------------------------
// Fused kernel, one warp per feature row (8 rows / 256-thread block).
//  - Warp 0 of each block computes 1/||W_0||, 1/||W_1|| into smem (W is 4KB,
//    L1-resident after the first block touches it). One __syncthreads.
//  - Per row: 4 front-batched feat LDG.128 (streaming, __ldcs), 8 W LDG.128
//    (L1 hits), 48 FMA, 3-value warp reduce, margin math on lane 0.
// ---------------------------------------------------------------------------
__global__ void __launch_bounds__(256, 8)
arcface_kernel(const float* __restrict__ feat,
               const float* __restrict__ W,
               const int*   __restrict__ label,
               float*       __restrict__ out,
               int B)
{
    __shared__ float s_invw[2];

    const int tid  = threadIdx.x;
    const int wid  = tid >> 5;
    const int lane = tid & 31;

    const float4* __restrict__ W4 = reinterpret_cast<const float4*>(W);

    // ---- Once per block: inverse norms of the two W rows ----
    if (wid == 0) {
        float ssw0 = 0.0f, ssw1 = 0.0f;
        #pragma unroll
        for (int k = 0; k < 4; k++) {
            const int idx = lane + 32 * k;
            float4 b = W4[idx];
            float4 c = W4[128 + idx];
            ssw0 = fmaf(b.x, b.x, ssw0); ssw0 = fmaf(b.y, b.y, ssw0);
            ssw0 = fmaf(b.z, b.z, ssw0); ssw0 = fmaf(b.w, b.w, ssw0);
            ssw1 = fmaf(c.x, c.x, ssw1); ssw1 = fmaf(c.y, c.y, ssw1);
            ssw1 = fmaf(c.z, c.z, ssw1); ssw1 = fmaf(c.w, c.w, ssw1);
        }
        #pragma unroll
        for (int o = 16; o > 0; o >>= 1) {
            ssw0 += __shfl_xor_sync(0xffffffff, ssw0, o);
            ssw1 += __shfl_xor_sync(0xffffffff, ssw1, o);
        }
        if (lane == 0) {
            s_invw[0] = 1.0f / fmaxf(sqrtf(ssw0), 1e-12f);
            s_invw[1] = 1.0f / fmaxf(sqrtf(ssw1), 1e-12f);
        }
    }
    __syncthreads();

    const int row = blockIdx.x * 8 + wid;
    if (row >= B) return;

    const float4* __restrict__ f =
        reinterpret_cast<const float4*>(feat + (size_t)row * 512);

    // ---- Front-batch the 4 streaming feat loads (max MLP, evict-first) ----
    float4 a0 = __ldcs(&f[lane]);
    float4 a1 = __ldcs(&f[lane + 32]);
    float4 a2 = __ldcs(&f[lane + 64]);
    float4 a3 = __ldcs(&f[lane + 96]);

    float ss = 0.0f, d0 = 0.0f, d1 = 0.0f;

    {
        float4 b, c;
        #define ACC(A, K)                                                     \
            b = W4[lane + 32 * (K)];                                          \
            c = W4[128 + lane + 32 * (K)];                                    \
            ss = fmaf(A.x, A.x, ss); ss = fmaf(A.y, A.y, ss);                 \
            ss = fmaf(A.z, A.z, ss); ss = fmaf(A.w, A.w, ss);                 \
            d0 = fmaf(A.x, b.x, d0); d0 = fmaf(A.y, b.y, d0);                 \
            d0 = fmaf(A.z, b.z, d0); d0 = fmaf(A.w, b.w, d0);                 \
            d1 = fmaf(A.x, c.x, d1); d1 = fmaf(A.y, c.y, d1);                 \
            d1 = fmaf(A.z, c.z, d1); d1 = fmaf(A.w, c.w, d1);
        ACC(a0, 0)
        ACC(a1, 1)
        ACC(a2, 2)
        ACC(a3, 3)
        #undef ACC
    }

    #pragma unroll
    for (int o = 16; o > 0; o >>= 1) {
        ss += __shfl_xor_sync(0xffffffff, ss, o);
        d0 += __shfl_xor_sync(0xffffffff, d0, o);
        d1 += __shfl_xor_sync(0xffffffff, d1, o);
    }

    if (lane == 0) {
        const float invf = 1.0f / fmaxf(sqrtf(ss), 1e-12f);

        float c0 = fminf(fmaxf(d0 * invf * s_invw[0], -1.0f + EPS_CLIP), 1.0f - EPS_CLIP);
        float c1 = fminf(fmaxf(d1 * invf * s_invw[1], -1.0f + EPS_CLIP), 1.0f - EPS_CLIP);

        // cos(theta + m) = cos*cos_m - sin*sin_m, sin = sqrt(1-cos^2) >= 0
        float s0 = sqrtf(fmaxf(1.0f - c0 * c0, 0.0f));
        float s1 = sqrtf(fmaxf(1.0f - c1 * c1, 0.0f));
        float m0 = c0 * COS_M - s0 * SIN_M;
        float m1 = c1 * COS_M - s1 * SIN_M;

        const int lab = label[row];
        float o0 = (lab == 0) ? m0 : c0;
        float o1 = (lab == 1) ? m1 : c1;

        reinterpret_cast<float2*>(out)[row] = make_float2(o0 * SCALE, o1 * SCALE);
    }
}

// ---------------------------------------------------------------------------
// kernel_launch: identify inputs by element count (robust to ordering):
//   feat : B*D f32 (largest), W : C*D f32 (smallest), label : B int32
// ---------------------------------------------------------------------------
extern "C" void kernel_launch(void* const* d_in, const int* in_sizes, int n_in,
                              void* d_out, int out_size)
{
    int i_feat = 0, i_w = 0, i_lab = 0;
    for (int i = 1; i < n_in; i++) {
        if (in_sizes[i] > in_sizes[i_feat]) i_feat = i;
        if (in_sizes[i] < in_sizes[i_w])    i_w    = i;
    }
    for (int i = 0; i < n_in; i++)
        if (i != i_feat && i != i_w) i_lab = i;

    const float* feat  = (const float*)d_in[i_feat];
    const float* W     = (const float*)d_in[i_w];
    const int*   label = (const int*)d_in[i_lab];
    float*       out   = (float*)d_out;
    const int    B     = in_sizes[i_lab];

    const int blocks = (B + 7) / 8;       // 8 rows (warps) per block
    arcface_kernel<<<blocks, 256>>>(feat, W, label, out, B);
}

// round 7
// speedup vs baseline: 1.1286x; 1.0087x over previous
#include <cuda_runtime.h>
#include <math.h>

static constexpr float EPS_CLIP = 1e-7f;
static constexpr float SCALE    = 64.0f;
// cos(0.5), sin(0.5)
static constexpr float COS_M = 0.8775825618903728f;
static constexpr float SIN_M = 0.479425538604203f;

// ---------------------------------------------------------------------------
// Single fused kernel, one warp per feature row (8 rows / 256-thread block).
// Each warp loads the full W anyway for its dot products, so it also
// accumulates ||W0||^2, ||W1||^2 from the same registers — no prologue
// kernel, no smem, no __syncthreads, no cross-warp dependency.
// Per row: 4 feat LDG.128 + 8 W LDG.128 (L1 hits), 80 FMA, 5-value warp
// reduce, margin math on lane 0.
// ---------------------------------------------------------------------------
__global__ void __launch_bounds__(256, 8)
arcface_kernel(const float* __restrict__ feat,
               const float* __restrict__ W,
               const int*   __restrict__ label,
               float*       __restrict__ out,
               int B)
{
    const int row  = (blockIdx.x * blockDim.x + threadIdx.x) >> 5;
    const int lane = threadIdx.x & 31;
    if (row >= B) return;

    const float4* __restrict__ f =
        reinterpret_cast<const float4*>(feat + (size_t)row * 512);
    const float4* __restrict__ W4 = reinterpret_cast<const float4*>(W);

    float ss = 0.0f, d0 = 0.0f, d1 = 0.0f, sw0 = 0.0f, sw1 = 0.0f;

    #pragma unroll
    for (int k = 0; k < 4; k++) {
        const int idx = lane + 32 * k;       // 128 float4 per row
        float4 a = f[idx];
        float4 b = W4[idx];
        float4 c = W4[128 + idx];
        ss  = fmaf(a.x, a.x, ss);  ss  = fmaf(a.y, a.y, ss);
        ss  = fmaf(a.z, a.z, ss);  ss  = fmaf(a.w, a.w, ss);
        d0  = fmaf(a.x, b.x, d0);  d0  = fmaf(a.y, b.y, d0);
        d0  = fmaf(a.z, b.z, d0);  d0  = fmaf(a.w, b.w, d0);
        d1  = fmaf(a.x, c.x, d1);  d1  = fmaf(a.y, c.y, d1);
        d1  = fmaf(a.z, c.z, d1);  d1  = fmaf(a.w, c.w, d1);
        sw0 = fmaf(b.x, b.x, sw0); sw0 = fmaf(b.y, b.y, sw0);
        sw0 = fmaf(b.z, b.z, sw0); sw0 = fmaf(b.w, b.w, sw0);
        sw1 = fmaf(c.x, c.x, sw1); sw1 = fmaf(c.y, c.y, sw1);
        sw1 = fmaf(c.z, c.z, sw1); sw1 = fmaf(c.w, c.w, sw1);
    }

    #pragma unroll
    for (int o = 16; o > 0; o >>= 1) {
        ss  += __shfl_xor_sync(0xffffffff, ss,  o);
        d0  += __shfl_xor_sync(0xffffffff, d0,  o);
        d1  += __shfl_xor_sync(0xffffffff, d1,  o);
        sw0 += __shfl_xor_sync(0xffffffff, sw0, o);
        sw1 += __shfl_xor_sync(0xffffffff, sw1, o);
    }

    if (lane == 0) {
        const float invf  = 1.0f / fmaxf(sqrtf(ss),  1e-12f);
        const float invw0 = 1.0f / fmaxf(sqrtf(sw0), 1e-12f);
        const float invw1 = 1.0f / fmaxf(sqrtf(sw1), 1e-12f);

        float c0 = fminf(fmaxf(d0 * invf * invw0, -1.0f + EPS_CLIP), 1.0f - EPS_CLIP);
        float c1 = fminf(fmaxf(d1 * invf * invw1, -1.0f + EPS_CLIP), 1.0f - EPS_CLIP);

        // cos(theta + m) = cos*cos_m - sin*sin_m, sin = sqrt(1-cos^2) >= 0
        float s0 = sqrtf(fmaxf(1.0f - c0 * c0, 0.0f));
        float s1 = sqrtf(fmaxf(1.0f - c1 * c1, 0.0f));
        float m0 = c0 * COS_M - s0 * SIN_M;
        float m1 = c1 * COS_M - s1 * SIN_M;

        const int lab = label[row];
        float o0 = (lab == 0) ? m0 : c0;
        float o1 = (lab == 1) ? m1 : c1;

        reinterpret_cast<float2*>(out)[row] = make_float2(o0 * SCALE, o1 * SCALE);
    }
}

// ---------------------------------------------------------------------------
// kernel_launch: identify inputs by element count (robust to ordering):
//   feat : B*D f32 (largest), W : C*D f32 (smallest), label : B int32
// ---------------------------------------------------------------------------
extern "C" void kernel_launch(void* const* d_in, const int* in_sizes, int n_in,
                              void* d_out, int out_size)
{
    int i_feat = 0, i_w = 0, i_lab = 0;
    for (int i = 1; i < n_in; i++) {
        if (in_sizes[i] > in_sizes[i_feat]) i_feat = i;
        if (in_sizes[i] < in_sizes[i_w])    i_w    = i;
    }
    for (int i = 0; i < n_in; i++)
        if (i != i_feat && i != i_w) i_lab = i;

    const float* feat  = (const float*)d_in[i_feat];
    const float* W     = (const float*)d_in[i_w];
    const int*   label = (const int*)d_in[i_lab];
    float*       out   = (float*)d_out;
    const int    B     = in_sizes[i_lab];

    const int blocks = (B + 7) / 8;       // 8 rows (warps) per block
    arcface_kernel<<<blocks, 256>>>(feat, W, label, out, B);
}